// round 15
// baseline (speedup 1.0000x reference)
#include <cuda_runtime.h>
#include <math.h>

#define BB 32
#define SS 128
#define NC 128
#define DD 64
#define II 256
#define OD 8192   // NC*DD
#define TOFF (BB*NC*DD)

__device__ float g_PE1[NC * DD];
__device__ float g_PE2[SS * OD];        // 4 MB
__device__ float g_P  [BB * SS * DD];
__device__ float g_Su [BB * SS];
__device__ float g_q  [BB];
__device__ float g_mx [BB * SS];        // per-(b,s) softmax max
__device__ float g_sc [BB * SS];        // per-(b,s) mask/sum
__device__ float g_T  [2 * BB * NC * DD];
__device__ float g_V  [BB * NC * DD];
__device__ float g_Bl [BB * NC * SS];

// ---------------------------------------------------------------------------
// Init, 288 blocks: PE2 recurrence / PE1 / gemmP.
// ---------------------------------------------------------------------------
__global__ void __launch_bounds__(256) k_init(const float* __restrict__ u,
                                              const float* __restrict__ W) {
    __shared__ float shU[16][II];
    const float LN1E4 = 9.210340371976184f;
    if (blockIdx.x < 16) {
        int k = blockIdx.x * 256 + threadIdx.x;      // 0..4095
        float th = expf(-(float)k * (LN1E4 / 4096.0f));
        float sv, cv;
        sincosf(th, &sv, &cv);
        float sc = 0.f, cc = 1.f;
        float2* dst = (float2*)g_PE2;
        #pragma unroll 4
        for (int s = 0; s < SS; s++) {
            dst[s * (OD / 2) + k] = make_float2(sc, cc);
            float ns = sc * cv + cc * sv;
            float nc = cc * cv - sc * sv;
            sc = ns; cc = nc;
        }
        return;
    }
    if (blockIdx.x < 32) {
        int idx = (blockIdx.x - 16) * 256 + threadIdx.x;
        int n = idx >> 5, kk = idx & 31;
        float th = expf(-(float)kk * (LN1E4 / 32.0f));
        float sv, cv;
        sincosf((float)n * th, &sv, &cv);
        *(float2*)&g_PE1[n * DD + 2 * kk] = make_float2(sv, cv);
        return;
    }
    int row0 = (blockIdx.x - 32) * 16;
    for (int idx = threadIdx.x; idx < 16 * 64; idx += 256) {
        int r = idx >> 6, i = idx & 63;
        *(float4*)&shU[r][i * 4] = *(const float4*)&u[(row0 + r) * II + i * 4];
    }
    __syncthreads();
    int d = threadIdx.x & 63, g = threadIdx.x >> 6;
    const float4* u0 = (const float4*)&shU[g][0];
    const float4* u1 = (const float4*)&shU[g + 4][0];
    const float4* u2 = (const float4*)&shU[g + 8][0];
    const float4* u3 = (const float4*)&shU[g + 12][0];
    float a0 = 0, a1 = 0, a2 = 0, a3 = 0;
    #pragma unroll 8
    for (int i4 = 0; i4 < II / 4; i4++) {
        float4 f0 = u0[i4], f1 = u1[i4], f2 = u2[i4], f3 = u3[i4];
        float w0 = __ldg(&W[(i4 * 4 + 0) * DD + d]);
        float w1 = __ldg(&W[(i4 * 4 + 1) * DD + d]);
        float w2 = __ldg(&W[(i4 * 4 + 2) * DD + d]);
        float w3 = __ldg(&W[(i4 * 4 + 3) * DD + d]);
        a0 += f0.x * w0 + f0.y * w1 + f0.z * w2 + f0.w * w3;
        a1 += f1.x * w0 + f1.y * w1 + f1.z * w2 + f1.w * w3;
        a2 += f2.x * w0 + f2.y * w1 + f2.z * w2 + f2.w * w3;
        a3 += f3.x * w0 + f3.y * w1 + f3.z * w2 + f3.w * w3;
    }
    g_P[(row0 + g) * DD + d]      = a0;
    g_P[(row0 + g + 4) * DD + d]  = a1;
    g_P[(row0 + g + 8) * DD + d]  = a2;
    g_P[(row0 + g + 12) * DD + d] = a3;
    int r = threadIdx.x >> 4, t = threadIdx.x & 15;
    float sm = 0.f;
    for (int i = t; i < II; i += 16) sm += shU[r][i];
    sm += __shfl_xor_sync(0xffffffffu, sm, 8);
    sm += __shfl_xor_sync(0xffffffffu, sm, 4);
    sm += __shfl_xor_sync(0xffffffffu, sm, 2);
    sm += __shfl_xor_sync(0xffffffffu, sm, 1);
    if (t == 0) g_Su[row0 + r] = sm;
}

// ---------------------------------------------------------------------------
// Iter-0 shortcut: T0[b,d], q0[b]. grid = 32.
// ---------------------------------------------------------------------------
__global__ void __launch_bounds__(256) k_A0(const float* __restrict__ mask) {
    __shared__ float shT[4][64];
    __shared__ float shQ[4];
    int b = blockIdx.x;
    int d = threadIdx.x & 63, g = threadIdx.x >> 6;
    const float* Pb = &g_P[b * SS * DD];
    float a = 0.f, q = 0.f;
    for (int j = 0; j < 32; j++) {
        int s = g * 32 + j;
        float c = mask[b * SS + s] * (1.0f / 128.0f);
        a += c * Pb[s * DD + d];
        q += c * g_Su[b * SS + s];
    }
    shT[g][d] = a;
    if (d == 0) shQ[g] = q;
    __syncthreads();
    if (threadIdx.x < 64) {
        g_T[b * DD + threadIdx.x] =
            shT[0][threadIdx.x] + shT[1][threadIdx.x] +
            shT[2][threadIdx.x] + shT[3][threadIdx.x];
        if (threadIdx.x == 0) g_q[b] = shQ[0] + shQ[1] + shQ[2] + shQ[3];
    }
}

// ---------------------------------------------------------------------------
// Output terms 1+2, s-split halves. 512 threads; 64 n per block.
// grid = 32 b * 2 ntile * 2 half = 128. c rebuilt from Bl via exp inline.
// ---------------------------------------------------------------------------
__global__ void __launch_bounds__(512) k_outA() {
    __shared__ float  shP[64 * DD];     // 16 KB (s-half of P_b)
    __shared__ float4 shC4[64 * 16];    // 64 n x 64 s -> 16 KB
    __shared__ float4 shSu4[16];
    int half = blockIdx.x & 1;
    int n0   = ((blockIdx.x >> 1) & 1) * 64;
    int b    = blockIdx.x >> 2;
    int sb   = half * 64;
    for (int idx = threadIdx.x; idx < 64 * 16; idx += 512)
        *(float4*)&shP[idx * 4] = *(const float4*)&g_P[(b * SS + sb) * DD + idx * 4];
    for (int idx = threadIdx.x; idx < 64 * 16; idx += 512) {
        int nr = idx >> 4, sc = idx & 15;
        float4 bl = *(const float4*)&g_Bl[(b * NC + n0 + nr) * SS + sb + sc * 4];
        float4 m  = *(const float4*)&g_mx[b * SS + sb + sc * 4];
        float4 sl = *(const float4*)&g_sc[b * SS + sb + sc * 4];
        shC4[idx] = make_float4(__expf(bl.x - m.x) * sl.x, __expf(bl.y - m.y) * sl.y,
                                __expf(bl.z - m.z) * sl.z, __expf(bl.w - m.w) * sl.w);
    }
    if (threadIdx.x < 16)
        shSu4[threadIdx.x] = *(const float4*)&g_Su[b * SS + sb + threadIdx.x * 4];
    __syncthreads();
    int d = threadIdx.x & 63, g = threadIdx.x >> 6;   // g 0..7, 8 n each
    float* T = g_T + half * TOFF;
    #pragma unroll
    for (int nq = 0; nq < 2; nq++) {
        int nb = g * 8 + nq * 4;                       // local n base
        const float4* c0 = &shC4[(nb + 0) * 16];
        const float4* c1 = &shC4[(nb + 1) * 16];
        const float4* c2 = &shC4[(nb + 2) * 16];
        const float4* c3 = &shC4[(nb + 3) * 16];
        float a0 = 0, a1 = 0, a2 = 0, a3 = 0, q0 = 0, q1 = 0, q2 = 0, q3 = 0;
        #pragma unroll
        for (int s4 = 0; s4 < 16; s4++) {
            float4 f0 = c0[s4], f1 = c1[s4], f2 = c2[s4], f3 = c3[s4];
            float4 su = shSu4[s4];
            float p0 = shP[(s4 * 4 + 0) * DD + d];
            float p1 = shP[(s4 * 4 + 1) * DD + d];
            float p2 = shP[(s4 * 4 + 2) * DD + d];
            float p3 = shP[(s4 * 4 + 3) * DD + d];
            a0 += f0.x * p0 + f0.y * p1 + f0.z * p2 + f0.w * p3;
            a1 += f1.x * p0 + f1.y * p1 + f1.z * p2 + f1.w * p3;
            a2 += f2.x * p0 + f2.y * p1 + f2.z * p2 + f2.w * p3;
            a3 += f3.x * p0 + f3.y * p1 + f3.z * p2 + f3.w * p3;
            q0 += f0.x * su.x + f0.y * su.y + f0.z * su.z + f0.w * su.w;
            q1 += f1.x * su.x + f1.y * su.y + f1.z * su.z + f1.w * su.w;
            q2 += f2.x * su.x + f2.y * su.y + f2.z * su.z + f2.w * su.w;
            q3 += f3.x * su.x + f3.y * su.y + f3.z * su.z + f3.w * su.w;
        }
        int n = n0 + nb;
        T[(b * NC + n + 0) * DD + d] = a0 + q0 * g_PE1[(n + 0) * DD + d];
        T[(b * NC + n + 1) * DD + d] = a1 + q1 * g_PE1[(n + 1) * DD + d];
        T[(b * NC + n + 2) * DD + d] = a2 + q2 * g_PE1[(n + 2) * DD + d];
        T[(b * NC + n + 3) * DD + d] = a3 + q3 * g_PE1[(n + 3) * DD + d];
    }
}

// ---------------------------------------------------------------------------
// Output term 3 + squash + fused logit term 3. 512 threads; 16 b per block.
// grid = 128 n * 2 btile = 256. c rebuilt from Bl via exp inline (non-it0).
// ---------------------------------------------------------------------------
__global__ void __launch_bounds__(512) k_outB(float* __restrict__ dst, int final_,
                                              int it0, const float* __restrict__ mask) {
    __shared__ float  shPE2[SS * 68];   // 34.8 KB
    __shared__ float4 shC4[16 * 32];    // 8 KB
    __shared__ float  shV[16 * DD];     // 4 KB
    __shared__ float  shRed0[8][2];
    __shared__ float  shRed1[8][2];
    int n  = blockIdx.x >> 1;
    int b0 = (blockIdx.x & 1) * 16;
    float* Vout = final_ ? dst : g_V;
    for (int idx = threadIdx.x; idx < SS * 16; idx += 512) {
        int s = idx >> 4, c = idx & 15;
        *(float4*)&shPE2[s * 68 + c * 4] = *(const float4*)&g_PE2[s * OD + n * DD + c * 4];
    }
    {
        int idx = threadIdx.x;              // 512 = 16*32
        int bl = idx >> 5, sc = idx & 31;
        if (it0) {
            float4 m = *(const float4*)&mask[(b0 + bl) * SS + sc * 4];
            shC4[idx] = make_float4(m.x * (1.0f / 128.0f), m.y * (1.0f / 128.0f),
                                    m.z * (1.0f / 128.0f), m.w * (1.0f / 128.0f));
        } else {
            float4 bv = *(const float4*)&g_Bl[((b0 + bl) * NC + n) * SS + sc * 4];
            float4 m  = *(const float4*)&g_mx[(b0 + bl) * SS + sc * 4];
            float4 sl = *(const float4*)&g_sc[(b0 + bl) * SS + sc * 4];
            shC4[idx] = make_float4(__expf(bv.x - m.x) * sl.x, __expf(bv.y - m.y) * sl.y,
                                    __expf(bv.z - m.z) * sl.z, __expf(bv.w - m.w) * sl.w);
        }
    }
    __syncthreads();
    int d = threadIdx.x & 63, g = threadIdx.x >> 6;
    int lane = threadIdx.x & 31, wig = (threadIdx.x >> 5) & 1;
    const float4* c0 = &shC4[(g * 2 + 0) * 32];
    const float4* c1 = &shC4[(g * 2 + 1) * 32];
    float a0 = 0, a1 = 0;
    #pragma unroll
    for (int s4 = 0; s4 < 32; s4++) {
        float4 f0 = c0[s4], f1 = c1[s4];
        float p0 = shPE2[(s4 * 4 + 0) * 68 + d];
        float p1 = shPE2[(s4 * 4 + 1) * 68 + d];
        float p2 = shPE2[(s4 * 4 + 2) * 68 + d];
        float p3 = shPE2[(s4 * 4 + 3) * 68 + d];
        a0 += f0.x * p0 + f0.y * p1 + f0.z * p2 + f0.w * p3;
        a1 += f1.x * p0 + f1.y * p1 + f1.z * p2 + f1.w * p3;
    }
    int bA = b0 + g * 2, bBd = bA + 1;
    float val0, val1;
    if (it0) {
        float pe = g_PE1[n * DD + d];
        val0 = g_T[bA  * DD + d] + g_q[bA]  * pe + a0;
        val1 = g_T[bBd * DD + d] + g_q[bBd] * pe + a1;
    } else {
        val0 = g_T[(bA * NC + n) * DD + d] + g_T[TOFF + (bA * NC + n) * DD + d] + a0;
        val1 = g_T[(bBd * NC + n) * DD + d] + g_T[TOFF + (bBd * NC + n) * DD + d] + a1;
    }
    float ss0 = val0 * val0, ss1 = val1 * val1;
    #pragma unroll
    for (int off = 16; off; off >>= 1) {
        ss0 += __shfl_xor_sync(0xffffffffu, ss0, off);
        ss1 += __shfl_xor_sync(0xffffffffu, ss1, off);
    }
    if (lane == 0) { shRed0[g][wig] = ss0; shRed1[g][wig] = ss1; }
    __syncthreads();
    float t0 = shRed0[g][0] + shRed0[g][1];
    float t1 = shRed1[g][0] + shRed1[g][1];
    float sc0 = t0 / (1.0f + t0) * rsqrtf(t0 + 1e-7f);
    float sc1 = t1 / (1.0f + t1) * rsqrtf(t1 + 1e-7f);
    float v0w = sc0 * val0, v1w = sc1 * val1;
    Vout[(bA  * NC + n) * DD + d] = v0w;
    Vout[(bBd * NC + n) * DD + d] = v1w;
    if (final_) return;
    shV[(g * 2 + 0) * DD + d] = v0w;
    shV[(g * 2 + 1) * DD + d] = v1w;
    __syncthreads();
    // Phase 2: Bl[b,n,s] = sum_d V*PE2
    int s = threadIdx.x & 127, h = threadIdx.x >> 7;
    int bl = h * 4;
    const float4* pr = (const float4*)&shPE2[s * 68];
    const float4* w0 = (const float4*)&shV[(bl + 0) * DD];
    const float4* w1 = (const float4*)&shV[(bl + 1) * DD];
    const float4* w2 = (const float4*)&shV[(bl + 2) * DD];
    const float4* w3 = (const float4*)&shV[(bl + 3) * DD];
    float r0 = 0, r1 = 0, r2 = 0, r3 = 0;
    #pragma unroll
    for (int d4 = 0; d4 < 16; d4++) {
        float4 p = pr[d4];
        float4 x0 = w0[d4], x1 = w1[d4], x2 = w2[d4], x3 = w3[d4];
        r0 += p.x * x0.x + p.y * x0.y + p.z * x0.z + p.w * x0.w;
        r1 += p.x * x1.x + p.y * x1.y + p.z * x1.z + p.w * x1.w;
        r2 += p.x * x2.x + p.y * x2.y + p.z * x2.z + p.w * x2.w;
        r3 += p.x * x3.x + p.y * x3.y + p.z * x3.z + p.w * x3.w;
    }
    g_Bl[((b0 + bl + 0) * NC + n) * SS + s] = r0;
    g_Bl[((b0 + bl + 1) * NC + n) * SS + s] = r1;
    g_Bl[((b0 + bl + 2) * NC + n) * SS + s] = r2;
    g_Bl[((b0 + bl + 3) * NC + n) * SS + s] = r3;
}

// ---------------------------------------------------------------------------
// Logit terms 1+2 (accumulate onto term 3). 512 threads; 32 n per block.
// grid = 32 b * 4 ntile = 128 (single wave).
// ---------------------------------------------------------------------------
__global__ void __launch_bounds__(512) k_bA() {
    __shared__ float shP[SS * 68];   // 34.8 KB
    __shared__ float shV[32 * DD];   // 8 KB
    __shared__ float shSu[SS];
    __shared__ float shSc[32];
    int b  = blockIdx.x >> 2;
    int n0 = (blockIdx.x & 3) * 32;
    for (int idx = threadIdx.x; idx < SS * 16; idx += 512) {
        int s = idx >> 4, c = idx & 15;
        *(float4*)&shP[s * 68 + c * 4] = *(const float4*)&g_P[(b * SS + s) * DD + c * 4];
    }
    {
        int idx = threadIdx.x;              // 512 = 32*16 float4
        *(float4*)&shV[idx * 4] = *(const float4*)&g_V[(b * NC + n0) * DD + idx * 4];
    }
    if (threadIdx.x < SS) shSu[threadIdx.x] = g_Su[b * SS + threadIdx.x];
    __syncthreads();
    {
        // 16 warps cover 32 n (2 each): shSc[n_local] = dot(V, PE1)
        int w = threadIdx.x >> 5, lane = threadIdx.x & 31;
        #pragma unroll
        for (int j = 0; j < 2; j++) {
            int nl = w + j * 16;
            float t = shV[nl * DD + lane]      * g_PE1[(n0 + nl) * DD + lane]
                    + shV[nl * DD + 32 + lane] * g_PE1[(n0 + nl) * DD + 32 + lane];
            #pragma unroll
            for (int off = 16; off; off >>= 1)
                t += __shfl_xor_sync(0xffffffffu, t, off);
            if (lane == 0) shSc[nl] = t;
        }
    }
    __syncthreads();
    int s = threadIdx.x & 127, h = threadIdx.x >> 7;  // h 0..3, 8 n each
    const float4* pr = (const float4*)&shP[s * 68];
    float su = shSu[s];
    #pragma unroll
    for (int nq = 0; nq < 2; nq++) {
        int nl = h * 8 + nq * 4;
        const float4* v0 = (const float4*)&shV[(nl + 0) * DD];
        const float4* v1 = (const float4*)&shV[(nl + 1) * DD];
        const float4* v2 = (const float4*)&shV[(nl + 2) * DD];
        const float4* v3 = (const float4*)&shV[(nl + 3) * DD];
        float a0 = 0, a1 = 0, a2 = 0, a3 = 0;
        #pragma unroll
        for (int d4 = 0; d4 < 16; d4++) {
            float4 p = pr[d4];
            float4 w0 = v0[d4], w1 = v1[d4], w2 = v2[d4], w3 = v3[d4];
            a0 += p.x * w0.x + p.y * w0.y + p.z * w0.z + p.w * w0.w;
            a1 += p.x * w1.x + p.y * w1.y + p.z * w1.z + p.w * w1.w;
            a2 += p.x * w2.x + p.y * w2.y + p.z * w2.z + p.w * w2.w;
            a3 += p.x * w3.x + p.y * w3.y + p.z * w3.z + p.w * w3.w;
        }
        g_Bl[(b * NC + n0 + nl + 0) * SS + s] += a0 + su * shSc[nl + 0];
        g_Bl[(b * NC + n0 + nl + 1) * SS + s] += a1 + su * shSc[nl + 1];
        g_Bl[(b * NC + n0 + nl + 2) * SS + s] += a2 + su * shSc[nl + 2];
        g_Bl[(b * NC + n0 + nl + 3) * SS + s] += a3 + su * shSc[nl + 3];
    }
}

// ---------------------------------------------------------------------------
// Softmax reduction only: mx[b,s] = max_n Bl, sc[b,s] = mask/sum_n exp(Bl-mx).
// grid = 128 (b x 4 s-tiles), 256 threads (8 warps x 16 n).
// ---------------------------------------------------------------------------
__global__ void __launch_bounds__(256) k_red(const float* __restrict__ mask) {
    __shared__ float red[2][8][32];
    int b = blockIdx.x >> 2, s0 = (blockIdx.x & 3) * 32;
    int lane = threadIdx.x & 31, w = threadIdx.x >> 5;
    int s = s0 + lane;
    float v[16];
    float mx = -1e30f;
    #pragma unroll
    for (int j = 0; j < 16; j++) {
        v[j] = g_Bl[(b * NC + w * 16 + j) * SS + s];
        mx = fmaxf(mx, v[j]);
    }
    red[0][w][lane] = mx;
    __syncthreads();
    mx = red[0][0][lane];
    #pragma unroll
    for (int w2 = 1; w2 < 8; w2++) mx = fmaxf(mx, red[0][w2][lane]);
    float sum = 0.f;
    #pragma unroll
    for (int j = 0; j < 16; j++) sum += __expf(v[j] - mx);
    red[1][w][lane] = sum;
    __syncthreads();
    sum = red[1][0][lane];
    #pragma unroll
    for (int w2 = 1; w2 < 8; w2++) sum += red[1][w2][lane];
    if (w == 0) {
        g_mx[b * SS + s] = mx;
        g_sc[b * SS + s] = mask[b * SS + s] / sum;
    }
}

// ---------------------------------------------------------------------------
extern "C" void kernel_launch(void* const* d_in, const int* in_sizes, int n_in,
                              void* d_out, int out_size) {
    const float* u    = (const float*)d_in[0];
    const float* mask = (const float*)d_in[1];
    const float* W    = (const float*)d_in[2];
    float* out = (float*)d_out;

    k_init<<<288, 256>>>(u, W);
    k_A0<<<32, 256>>>(mask);

    // iteration 0 (c = mask/128; outA replaced by A0)
    k_outB<<<256, 512>>>(out, 0, 1, mask);
    k_bA<<<128, 512>>>();
    k_red<<<128, 256>>>(mask);
    // iteration 1
    k_outA<<<128, 512>>>();
    k_outB<<<256, 512>>>(out, 0, 0, mask);
    k_bA<<<128, 512>>>();
    k_red<<<128, 256>>>(mask);
    // iteration 2
    k_outA<<<128, 512>>>();
    k_outB<<<256, 512>>>(out, 1, 0, mask);
}